// round 14
// baseline (speedup 1.0000x reference)
#include <cuda_runtime.h>

// ----------------------------------------------------------------------------
// WCT: group whitening/coloring transform.
// Outputs (concatenated in d_out): out[4,256,128,128], cov_c[8,32,32],
// eigen_s[32,32,32].
// ----------------------------------------------------------------------------

#define ULL unsigned long long

static __device__ float g_gram[8 * 32 * 32];   // raw per-group sum x x^T
static __device__ float g_csum[256];           // per-channel sums
static __device__ float g_mean[256];           // per-channel means
static __device__ float g_ct[32 * 1024];       // ct MLP output [B*G, 1024]
static __device__ float g_mu[4 * 256];         // mu MLP output [B, 256]
static __device__ float g_Ms[32 * 32 * 32];    // [b*8+g][i][k]: alpha*UDU + (1-a)I
static __device__ float g_bias[4 * 256];       // alpha*(s_mu - UDU @ mean)

constexpr int HW = 16384;              // 128*128
constexpr float INV_N = 1.0f / 65536.0f;
constexpr float INV_NM1 = 1.0f / 65535.0f;

// ---- packed f32x2 helpers (FFMA2: 2 fp32 MACs / instruction) ----------------
__device__ __forceinline__ ULL fma2(ULL a, ULL b, ULL c) {
    ULL d;
    asm("fma.rn.f32x2 %0, %1, %2, %3;" : "=l"(d) : "l"(a), "l"(b), "l"(c));
    return d;
}
__device__ __forceinline__ ULL add2(ULL a, ULL b) {
    ULL d;
    asm("add.rn.f32x2 %0, %1, %2;" : "=l"(d) : "l"(a), "l"(b));
    return d;
}
__device__ __forceinline__ ULL pack2(float lo, float hi) {
    ULL d;
    asm("mov.b64 %0, {%1, %2};" : "=l"(d) : "f"(lo), "f"(hi));
    return d;
}
__device__ __forceinline__ float sum2f(ULL a) {
    float lo, hi;
    asm("mov.b64 {%0, %1}, %2;" : "=f"(lo), "=f"(hi) : "l"(a));
    return lo + hi;
}

// ---- zero the accumulators (graph replays must start clean) -----------------
__global__ void k_zero() {
    int t = blockIdx.x * 256 + threadIdx.x;
    if (t < 8192) g_gram[t] = 0.0f;
    else if (t < 8448) g_csum[t - 8192] = 0.0f;
}

// ---- generic MLP layer: one block = one independent row ---------------------
// out[o] = dot(W[o,:], in) + bias[o], optional LeakyReLU(0.01).
__device__ __forceinline__ void mlp_layer(const float* __restrict__ W,
                                          const float* __restrict__ Bv,
                                          const float* __restrict__ in,
                                          float* out, int in_dim, int out_dim,
                                          bool act) {
    int warp = threadIdx.x >> 5, lane = threadIdx.x & 31;
    for (int o = warp; o < out_dim; o += 8) {
        const float* wr = W + o * in_dim;
        float acc = 0.0f;
        for (int i = lane * 4; i < in_dim; i += 128) {
            float4 w4 = *(const float4*)(wr + i);
            acc += w4.x * in[i] + w4.y * in[i + 1] + w4.z * in[i + 2] + w4.w * in[i + 3];
        }
#pragma unroll
        for (int off = 16; off; off >>= 1)
            acc += __shfl_xor_sync(0xffffffffu, acc, off);
        if (lane == 0) {
            float v = acc + Bv[o];
            if (act && v < 0.0f) v *= 0.01f;
            out[o] = v;
        }
    }
    __syncthreads();
}

__global__ void __launch_bounds__(256) k_mlp_ct(
    const float* __restrict__ sB,
    const float* __restrict__ w0, const float* __restrict__ b0,
    const float* __restrict__ w1, const float* __restrict__ b1,
    const float* __restrict__ w2, const float* __restrict__ b2,
    const float* __restrict__ w3, const float* __restrict__ b3,
    const float* __restrict__ w4, const float* __restrict__ b4) {
    __shared__ float A[256], Bf[256];
    int r = blockIdx.x;  // row of s_B.reshape(32, 32)
    if (threadIdx.x < 32) A[threadIdx.x] = sB[r * 32 + threadIdx.x];
    __syncthreads();
    mlp_layer(w0, b0, A, Bf, 32, 256, true);
    mlp_layer(w1, b1, Bf, A, 256, 256, true);
    mlp_layer(w2, b2, A, Bf, 256, 256, true);
    mlp_layer(w3, b3, Bf, A, 256, 256, true);
    mlp_layer(w4, b4, A, g_ct + r * 1024, 256, 1024, false);
}

__global__ void __launch_bounds__(256) k_mlp_mu(
    const float* __restrict__ sB,
    const float* __restrict__ w0, const float* __restrict__ b0,
    const float* __restrict__ w1, const float* __restrict__ b1,
    const float* __restrict__ w2, const float* __restrict__ b2) {
    __shared__ float A[256], Bf[256];
    int r = blockIdx.x;  // batch index
    A[threadIdx.x] = sB[r * 256 + threadIdx.x];
    __syncthreads();
    mlp_layer(w0, b0, A, Bf, 256, 256, true);
    mlp_layer(w1, b1, Bf, A, 256, 256, true);
    mlp_layer(w2, b2, A, g_mu + r * 256, 256, 256, false);
}

// ---- stats: per-group raw Gram (sum x x^T) + channel sums, single c_A pass --
// grid = 256 blocks: g = bid&7, chunk = bid>>3 (b = chunk>>3, hw0 = (chunk&7)*2048)
__global__ void __launch_bounds__(256) k_stats(const float* __restrict__ cA) {
    __shared__ float xs[32 * 260];  // 32 ch x 256 samples, pad-4 stride
    int g = blockIdx.x & 7;
    int chunk = blockIdx.x >> 3;
    int b = chunk >> 3;
    int hw0 = (chunk & 7) * 2048;
    int t = threadIdx.x;
    int unit = t >> 6;       // 4 units of 64 threads, split sample-pairs
    int u = t & 63;
    int ur = u & 7;          // row group: rows ur + 8r
    int uc = u >> 3;         // col group: cols uc + 8c

    ULL acc[4][4];
    ULL sum2[4];
#pragma unroll
    for (int r = 0; r < 4; r++) {
        sum2[r] = 0ull;
#pragma unroll
        for (int c = 0; c < 4; c++) acc[r][c] = 0ull;
    }

    const float* gbase = cA + (size_t)(b * 256 + g * 32) * HW + hw0;

    for (int stage = 0; stage < 8; ++stage) {
        const float* gs = gbase + stage * 256;
#pragma unroll
        for (int kk = 0; kk < 8; ++kk) {
            int gidx = t + 256 * kk;        // 0..2047 float4s
            int row = gidx >> 6, c4 = gidx & 63;
            float4 v = *(const float4*)(gs + (size_t)row * HW + c4 * 4);
            *(float4*)&xs[row * 260 + c4 * 4] = v;
        }
        __syncthreads();
#pragma unroll 2
        for (int m = 0; m < 32; ++m) {
            int soff = (unit + 4 * m) * 2;  // 2 samples packed per f32x2
            ULL xi[4], xj[4];
#pragma unroll
            for (int r = 0; r < 4; r++)
                xi[r] = *(const ULL*)&xs[(ur + 8 * r) * 260 + soff];
#pragma unroll
            for (int c = 0; c < 4; c++)
                xj[c] = *(const ULL*)&xs[(uc + 8 * c) * 260 + soff];
#pragma unroll
            for (int r = 0; r < 4; r++)
#pragma unroll
                for (int c = 0; c < 4; c++)
                    acc[r][c] = fma2(xi[r], xj[c], acc[r][c]);
            if (uc == 0) {
#pragma unroll
                for (int r = 0; r < 4; r++) sum2[r] = add2(sum2[r], xi[r]);
            }
        }
        __syncthreads();
    }

#pragma unroll
    for (int r = 0; r < 4; r++) {
        int i = ur + 8 * r;
#pragma unroll
        for (int c = 0; c < 4; c++) {
            int j = uc + 8 * c;
            atomicAdd(&g_gram[g * 1024 + i * 32 + j], sum2f(acc[r][c]));
        }
        if (uc == 0) atomicAdd(&g_csum[g * 32 + i], sum2f(sum2[r]));
    }
}

// ---- finalize covariance output + means -------------------------------------
__global__ void k_fincov(float* __restrict__ cov_out) {
    int g = blockIdx.x;
    int t = threadIdx.x;
    if (t < 32) g_mean[g * 32 + t] = g_csum[g * 32 + t] * INV_N;
#pragma unroll
    for (int k = 0; k < 4; ++k) {
        int idx = t + 256 * k;
        int i = idx >> 5, j = idx & 31;
        float si = g_csum[g * 32 + i], sj = g_csum[g * 32 + j];
        float v = (g_gram[g * 1024 + idx] - si * sj * INV_N) * INV_NM1;
        if (i == j) v += 1e-5f;
        cov_out[g * 1024 + idx] = v;
    }
}

// ---- U, eigen_s, UDU -> Ms (pre-blended) + bias ------------------------------
__global__ void __launch_bounds__(1024) k_udu(float* __restrict__ eig_out) {
    __shared__ float s[32 * 33], uu[32 * 33], ud[32 * 33], D[32];
    int r = blockIdx.x;          // b*8 + g
    int b = r >> 3, g = r & 7;
    int t = threadIdx.x;
    int i = t >> 5, j = t & 31;
    s[i * 33 + j] = g_ct[r * 1024 + t];
    __syncthreads();
    if (i == 0) {
        float acc = 0.0f;
        for (int ii = 0; ii < 32; ++ii) {
            float v = s[ii * 33 + j];
            acc += v * v;
        }
        D[j] = sqrtf(acc);
    }
    __syncthreads();
    float uval = s[i * 33 + j] / D[j];
    uu[i * 33 + j] = uval;
    eig_out[(g * 4 + b) * 1024 + t] = uval;  // eigen_s index g*B + b
    __syncthreads();
    float acc = 0.0f;
#pragma unroll
    for (int jj = 0; jj < 32; ++jj) acc += s[i * 33 + jj] * uu[j * 33 + jj];
    ud[i * 33 + j] = acc;
    g_Ms[r * 1024 + t] = 0.4f * acc + (i == j ? 0.6f : 0.0f);
    __syncthreads();
    if (t < 32) {
        float dot = 0.0f;
        for (int d = 0; d < 32; ++d) dot += ud[t * 33 + d] * g_mean[g * 32 + d];
        g_bias[b * 256 + g * 32 + t] = 0.4f * (g_mu[b * 256 + g * 32 + t] - dot);
    }
}

// ---- coloring pass: per (b,g): out[32,HW] = Ms @ x + bias --------------------
// grid = 512: bg = bid>>4, chunk = bid&15 (1024 hw each). 4 hw per thread via
// two f32x2 accumulator sets.
__global__ void __launch_bounds__(256) k_colored(const float* __restrict__ cA,
                                                 float* __restrict__ out) {
    __shared__ ULL m2[1024];   // m2[d*32 + i] = {Ms[i][d], Ms[i][d]}
    __shared__ ULL bias2[32];
    int bg = blockIdx.x >> 4;
    int chunk = blockIdx.x & 15;
    int t = threadIdx.x;
#pragma unroll
    for (int k = 0; k < 4; ++k) {
        int idx = t + 256 * k;  // idx = i*32 + d
        float f = g_Ms[bg * 1024 + idx];
        m2[(idx & 31) * 32 + (idx >> 5)] = pack2(f, f);
    }
    if (t < 32) {
        float bv = g_bias[bg * 32 + t];  // bg*32 == b*256 + g*32
        bias2[t] = pack2(bv, bv);
    }
    __syncthreads();

    size_t base = (size_t)bg * 32 * HW + (size_t)chunk * 1024;
    const ULL* src = (const ULL*)(cA + base);
    ULL* dst = (ULL*)(out + base);

    ULL acca[32], accb[32];
#pragma unroll
    for (int i = 0; i < 32; ++i) {
        acca[i] = bias2[i];
        accb[i] = bias2[i];
    }
#pragma unroll 4
    for (int d = 0; d < 32; ++d) {
        ULL xa = src[(size_t)d * 8192 + t];
        ULL xb = src[(size_t)d * 8192 + 256 + t];
#pragma unroll
        for (int i = 0; i < 32; ++i) {
            ULL m = m2[d * 32 + i];
            acca[i] = fma2(xa, m, acca[i]);
            accb[i] = fma2(xb, m, accb[i]);
        }
    }
#pragma unroll 4
    for (int i = 0; i < 32; ++i) {
        dst[(size_t)i * 8192 + t] = acca[i];
        dst[(size_t)i * 8192 + 256 + t] = accb[i];
    }
}

// -----------------------------------------------------------------------------
extern "C" void kernel_launch(void* const* d_in, const int* in_sizes, int n_in,
                              void* d_out, int out_size) {
    const float* cA = (const float*)d_in[0];
    const float* sB = (const float*)d_in[1];
    // d_in[2] = mask (block-diagonal structure is hardcoded)
    const float* ctw0 = (const float*)d_in[3];
    const float* ctb0 = (const float*)d_in[4];
    const float* ctw1 = (const float*)d_in[5];
    const float* ctb1 = (const float*)d_in[6];
    const float* ctw2 = (const float*)d_in[7];
    const float* ctb2 = (const float*)d_in[8];
    const float* ctw3 = (const float*)d_in[9];
    const float* ctb3 = (const float*)d_in[10];
    const float* ctw4 = (const float*)d_in[11];
    const float* ctb4 = (const float*)d_in[12];
    const float* muw0 = (const float*)d_in[13];
    const float* mub0 = (const float*)d_in[14];
    const float* muw1 = (const float*)d_in[15];
    const float* mub1 = (const float*)d_in[16];
    const float* muw2 = (const float*)d_in[17];
    const float* mub2 = (const float*)d_in[18];

    float* out = (float*)d_out;
    float* cov = out + 16777216;   // 4*256*128*128
    float* eig = cov + 8192;       // 8*32*32

    k_zero<<<33, 256>>>();
    k_mlp_ct<<<32, 256>>>(sB, ctw0, ctb0, ctw1, ctb1, ctw2, ctb2, ctw3, ctb3,
                          ctw4, ctb4);
    k_mlp_mu<<<4, 256>>>(sB, muw0, mub0, muw1, mub1, muw2, mub2);
    k_stats<<<256, 256>>>(cA);
    k_fincov<<<8, 256>>>(cov);
    k_udu<<<32, 1024>>>(eig);
    k_colored<<<512, 256>>>(cA, out);
}

// round 15
// speedup vs baseline: 1.0050x; 1.0050x over previous
#include <cuda_runtime.h>

// ----------------------------------------------------------------------------
// WCT: group whitening/coloring transform.
// Outputs (concatenated in d_out): out[4,256,128,128], cov_c[8,32,32],
// eigen_s[32,32,32].
// ----------------------------------------------------------------------------

#define ULL unsigned long long

static __device__ float g_gram[8 * 32 * 32];   // raw per-group sum x x^T
static __device__ float g_csum[256];           // per-channel sums
static __device__ float g_mean[256];           // per-channel means
static __device__ float g_ct[32 * 1024];       // ct MLP output [B*G, 1024]
static __device__ float g_mu[4 * 256];         // mu MLP output [B, 256]
static __device__ float g_Ms[32 * 32 * 32];    // [b*8+g][i][k]: alpha*UDU + (1-a)I
static __device__ float g_bias[4 * 256];       // alpha*(s_mu - UDU @ mean)

constexpr int HW = 16384;              // 128*128
constexpr float INV_N = 1.0f / 65536.0f;
constexpr float INV_NM1 = 1.0f / 65535.0f;

// ---- packed f32x2 helpers (FFMA2: 2 fp32 MACs / instruction) ----------------
__device__ __forceinline__ ULL fma2(ULL a, ULL b, ULL c) {
    ULL d;
    asm("fma.rn.f32x2 %0, %1, %2, %3;" : "=l"(d) : "l"(a), "l"(b), "l"(c));
    return d;
}
__device__ __forceinline__ ULL add2(ULL a, ULL b) {
    ULL d;
    asm("add.rn.f32x2 %0, %1, %2;" : "=l"(d) : "l"(a), "l"(b));
    return d;
}
__device__ __forceinline__ ULL pack2(float lo, float hi) {
    ULL d;
    asm("mov.b64 %0, {%1, %2};" : "=l"(d) : "f"(lo), "f"(hi));
    return d;
}
__device__ __forceinline__ float sum2f(ULL a) {
    float lo, hi;
    asm("mov.b64 {%0, %1}, %2;" : "=f"(lo), "=f"(hi) : "l"(a));
    return lo + hi;
}

// ---- zero the accumulators (graph replays must start clean) -----------------
__global__ void k_zero() {
    int t = blockIdx.x * 256 + threadIdx.x;
    if (t < 8192) g_gram[t] = 0.0f;
    else if (t < 8448) g_csum[t - 8192] = 0.0f;
}

// ---- generic MLP layer: one block = one independent row ---------------------
// out[o] = dot(W[o,:], in) + bias[o], optional LeakyReLU(0.01).
__device__ __forceinline__ void mlp_layer(const float* __restrict__ W,
                                          const float* __restrict__ Bv,
                                          const float* __restrict__ in,
                                          float* out, int in_dim, int out_dim,
                                          bool act) {
    int warp = threadIdx.x >> 5, lane = threadIdx.x & 31;
    for (int o = warp; o < out_dim; o += 8) {
        const float* wr = W + o * in_dim;
        float acc = 0.0f;
        for (int i = lane * 4; i < in_dim; i += 128) {
            float4 w4 = *(const float4*)(wr + i);
            acc += w4.x * in[i] + w4.y * in[i + 1] + w4.z * in[i + 2] + w4.w * in[i + 3];
        }
#pragma unroll
        for (int off = 16; off; off >>= 1)
            acc += __shfl_xor_sync(0xffffffffu, acc, off);
        if (lane == 0) {
            float v = acc + Bv[o];
            if (act && v < 0.0f) v *= 0.01f;
            out[o] = v;
        }
    }
    __syncthreads();
}

__global__ void __launch_bounds__(256) k_mlp_ct(
    const float* __restrict__ sB,
    const float* __restrict__ w0, const float* __restrict__ b0,
    const float* __restrict__ w1, const float* __restrict__ b1,
    const float* __restrict__ w2, const float* __restrict__ b2,
    const float* __restrict__ w3, const float* __restrict__ b3,
    const float* __restrict__ w4, const float* __restrict__ b4) {
    __shared__ float A[256], Bf[256];
    int r = blockIdx.x;  // row of s_B.reshape(32, 32)
    if (threadIdx.x < 32) A[threadIdx.x] = sB[r * 32 + threadIdx.x];
    __syncthreads();
    mlp_layer(w0, b0, A, Bf, 32, 256, true);
    mlp_layer(w1, b1, Bf, A, 256, 256, true);
    mlp_layer(w2, b2, A, Bf, 256, 256, true);
    mlp_layer(w3, b3, Bf, A, 256, 256, true);
    mlp_layer(w4, b4, A, g_ct + r * 1024, 256, 1024, false);
}

__global__ void __launch_bounds__(256) k_mlp_mu(
    const float* __restrict__ sB,
    const float* __restrict__ w0, const float* __restrict__ b0,
    const float* __restrict__ w1, const float* __restrict__ b1,
    const float* __restrict__ w2, const float* __restrict__ b2) {
    __shared__ float A[256], Bf[256];
    int r = blockIdx.x;  // batch index
    A[threadIdx.x] = sB[r * 256 + threadIdx.x];
    __syncthreads();
    mlp_layer(w0, b0, A, Bf, 256, 256, true);
    mlp_layer(w1, b1, Bf, A, 256, 256, true);
    mlp_layer(w2, b2, A, g_mu + r * 256, 256, 256, false);
}

// ---- stats: per-group raw Gram (sum x x^T) + channel sums, single c_A pass --
// grid = 256 blocks: g = bid&7, chunk = bid>>3 (b = chunk>>3, hw0 = (chunk&7)*2048)
__global__ void __launch_bounds__(256) k_stats(const float* __restrict__ cA) {
    __shared__ float xs[32 * 260];  // 32 ch x 256 samples, pad-4 stride
    int g = blockIdx.x & 7;
    int chunk = blockIdx.x >> 3;
    int b = chunk >> 3;
    int hw0 = (chunk & 7) * 2048;
    int t = threadIdx.x;
    int unit = t >> 6;       // 4 units of 64 threads, split sample-pairs
    int u = t & 63;
    int ur = u & 7;          // row group: rows ur + 8r
    int uc = u >> 3;         // col group: cols uc + 8c

    ULL acc[4][4];
    ULL sum2[4];
#pragma unroll
    for (int r = 0; r < 4; r++) {
        sum2[r] = 0ull;
#pragma unroll
        for (int c = 0; c < 4; c++) acc[r][c] = 0ull;
    }

    const float* gbase = cA + (size_t)(b * 256 + g * 32) * HW + hw0;

    for (int stage = 0; stage < 8; ++stage) {
        const float* gs = gbase + stage * 256;
#pragma unroll
        for (int kk = 0; kk < 8; ++kk) {
            int gidx = t + 256 * kk;        // 0..2047 float4s
            int row = gidx >> 6, c4 = gidx & 63;
            float4 v = *(const float4*)(gs + (size_t)row * HW + c4 * 4);
            *(float4*)&xs[row * 260 + c4 * 4] = v;
        }
        __syncthreads();
#pragma unroll 2
        for (int m = 0; m < 32; ++m) {
            int soff = (unit + 4 * m) * 2;  // 2 samples packed per f32x2
            ULL xi[4], xj[4];
#pragma unroll
            for (int r = 0; r < 4; r++)
                xi[r] = *(const ULL*)&xs[(ur + 8 * r) * 260 + soff];
#pragma unroll
            for (int c = 0; c < 4; c++)
                xj[c] = *(const ULL*)&xs[(uc + 8 * c) * 260 + soff];
#pragma unroll
            for (int r = 0; r < 4; r++)
#pragma unroll
                for (int c = 0; c < 4; c++)
                    acc[r][c] = fma2(xi[r], xj[c], acc[r][c]);
            if (uc == 0) {
#pragma unroll
                for (int r = 0; r < 4; r++) sum2[r] = add2(sum2[r], xi[r]);
            }
        }
        __syncthreads();
    }

#pragma unroll
    for (int r = 0; r < 4; r++) {
        int i = ur + 8 * r;
#pragma unroll
        for (int c = 0; c < 4; c++) {
            int j = uc + 8 * c;
            atomicAdd(&g_gram[g * 1024 + i * 32 + j], sum2f(acc[r][c]));
        }
        if (uc == 0) atomicAdd(&g_csum[g * 32 + i], sum2f(sum2[r]));
    }
}

// ---- finalize covariance output + means -------------------------------------
__global__ void k_fincov(float* __restrict__ cov_out) {
    int g = blockIdx.x;
    int t = threadIdx.x;
    if (t < 32) g_mean[g * 32 + t] = g_csum[g * 32 + t] * INV_N;
#pragma unroll
    for (int k = 0; k < 4; ++k) {
        int idx = t + 256 * k;
        int i = idx >> 5, j = idx & 31;
        float si = g_csum[g * 32 + i], sj = g_csum[g * 32 + j];
        float v = (g_gram[g * 1024 + idx] - si * sj * INV_N) * INV_NM1;
        if (i == j) v += 1e-5f;
        cov_out[g * 1024 + idx] = v;
    }
}

// ---- U, eigen_s, UDU -> Ms (pre-blended) + bias ------------------------------
__global__ void __launch_bounds__(1024) k_udu(float* __restrict__ eig_out) {
    __shared__ float s[32 * 33], uu[32 * 33], ud[32 * 33], D[32];
    int r = blockIdx.x;          // b*8 + g
    int b = r >> 3, g = r & 7;
    int t = threadIdx.x;
    int i = t >> 5, j = t & 31;
    s[i * 33 + j] = g_ct[r * 1024 + t];
    __syncthreads();
    if (i == 0) {
        float acc = 0.0f;
        for (int ii = 0; ii < 32; ++ii) {
            float v = s[ii * 33 + j];
            acc += v * v;
        }
        D[j] = sqrtf(acc);
    }
    __syncthreads();
    float uval = s[i * 33 + j] / D[j];
    uu[i * 33 + j] = uval;
    eig_out[(g * 4 + b) * 1024 + t] = uval;  // eigen_s index g*B + b
    __syncthreads();
    float acc = 0.0f;
#pragma unroll
    for (int jj = 0; jj < 32; ++jj) acc += s[i * 33 + jj] * uu[j * 33 + jj];
    ud[i * 33 + j] = acc;
    g_Ms[r * 1024 + t] = 0.4f * acc + (i == j ? 0.6f : 0.0f);
    __syncthreads();
    if (t < 32) {
        float dot = 0.0f;
        for (int d = 0; d < 32; ++d) dot += ud[t * 33 + d] * g_mean[g * 32 + d];
        g_bias[b * 256 + g * 32 + t] = 0.4f * (g_mu[b * 256 + g * 32 + t] - dot);
    }
}

// ---- coloring pass: per (b,g): out[32,HW] = Ms @ x + bias --------------------
// grid = 512: bg = bid>>4, chunk = bid&15 (1024 hw each). 4 hw per thread via
// two f32x2 accumulator sets.
__global__ void __launch_bounds__(256) k_colored(const float* __restrict__ cA,
                                                 float* __restrict__ out) {
    __shared__ ULL m2[1024];   // m2[d*32 + i] = {Ms[i][d], Ms[i][d]}
    __shared__ ULL bias2[32];
    int bg = blockIdx.x >> 4;
    int chunk = blockIdx.x & 15;
    int t = threadIdx.x;
#pragma unroll
    for (int k = 0; k < 4; ++k) {
        int idx = t + 256 * k;  // idx = i*32 + d
        float f = g_Ms[bg * 1024 + idx];
        m2[(idx & 31) * 32 + (idx >> 5)] = pack2(f, f);
    }
    if (t < 32) {
        float bv = g_bias[bg * 32 + t];  // bg*32 == b*256 + g*32
        bias2[t] = pack2(bv, bv);
    }
    __syncthreads();

    size_t base = (size_t)bg * 32 * HW + (size_t)chunk * 1024;
    const ULL* src = (const ULL*)(cA + base);
    ULL* dst = (ULL*)(out + base);

    ULL acca[32], accb[32];
#pragma unroll
    for (int i = 0; i < 32; ++i) {
        acca[i] = bias2[i];
        accb[i] = bias2[i];
    }
#pragma unroll 4
    for (int d = 0; d < 32; ++d) {
        ULL xa = src[(size_t)d * 8192 + t];
        ULL xb = src[(size_t)d * 8192 + 256 + t];
#pragma unroll
        for (int i = 0; i < 32; ++i) {
            ULL m = m2[d * 32 + i];
            acca[i] = fma2(xa, m, acca[i]);
            accb[i] = fma2(xb, m, accb[i]);
        }
    }
#pragma unroll 4
    for (int i = 0; i < 32; ++i) {
        dst[(size_t)i * 8192 + t] = acca[i];
        dst[(size_t)i * 8192 + 256 + t] = accb[i];
    }
}

// -----------------------------------------------------------------------------
extern "C" void kernel_launch(void* const* d_in, const int* in_sizes, int n_in,
                              void* d_out, int out_size) {
    const float* cA = (const float*)d_in[0];
    const float* sB = (const float*)d_in[1];
    // d_in[2] = mask (block-diagonal structure is hardcoded)
    const float* ctw0 = (const float*)d_in[3];
    const float* ctb0 = (const float*)d_in[4];
    const float* ctw1 = (const float*)d_in[5];
    const float* ctb1 = (const float*)d_in[6];
    const float* ctw2 = (const float*)d_in[7];
    const float* ctb2 = (const float*)d_in[8];
    const float* ctw3 = (const float*)d_in[9];
    const float* ctb3 = (const float*)d_in[10];
    const float* ctw4 = (const float*)d_in[11];
    const float* ctb4 = (const float*)d_in[12];
    const float* muw0 = (const float*)d_in[13];
    const float* mub0 = (const float*)d_in[14];
    const float* muw1 = (const float*)d_in[15];
    const float* mub1 = (const float*)d_in[16];
    const float* muw2 = (const float*)d_in[17];
    const float* mub2 = (const float*)d_in[18];

    float* out = (float*)d_out;
    float* cov = out + 16777216;   // 4*256*128*128
    float* eig = cov + 8192;       // 8*32*32

    k_zero<<<33, 256>>>();
    k_mlp_ct<<<32, 256>>>(sB, ctw0, ctb0, ctw1, ctb1, ctw2, ctb2, ctw3, ctb3,
                          ctw4, ctb4);
    k_mlp_mu<<<4, 256>>>(sB, muw0, mub0, muw1, mub1, muw2, mub2);
    k_stats<<<256, 256>>>(cA);
    k_fincov<<<8, 256>>>(cov);
    k_udu<<<32, 1024>>>(eig);
    k_colored<<<512, 256>>>(cA, out);
}